// round 9
// baseline (speedup 1.0000x reference)
#include <cuda_runtime.h>

#define NN   2048
#define ORD  3
#define PTS  16
#define DIM1 64
#define DIM2 32
#define PL1  32
#define PL2  8
#define LBL  10
#define TGRID 128               // k_tail blocks; 16 warps = 16 rows each

// Scratch (no allocations allowed)
__device__ float    g_ms[NN * ORD * PTS];   // [n, 48]
__device__ float    g_num[PL2 * DIM2];
__device__ float    g_den[PL2];
__device__ unsigned g_cnt;

__device__ __forceinline__ float fast_tanh(float x) {
    float r;
    asm("tanh.approx.f32 %0, %1;" : "=f"(r) : "f"(x));
    return r;
}

// cos(2*pi*y): exact reduction + even poly through (2*pi*t)^14, max err ~4e-6
__device__ __forceinline__ float cos2pi(float y) {
    float t = y - rintf(y);
    float u = t * t;
    float p = -1.7143907f;
    p = fmaf(p, u,  7.9035539f);
    p = fmaf(p, u, -26.4257337f);
    p = fmaf(p, u,  60.2446418f);
    p = fmaf(p, u, -85.4567987f);
    p = fmaf(p, u,  64.9393940f);
    p = fmaf(p, u, -19.7392088f);
    p = fmaf(p, u,  1.0f);
    return p;
}

__device__ __forceinline__ int bitrev3(int x) {
    return ((x & 1) << 2) | (x & 2) | ((x & 4) >> 2);
}

// ---------------------------------------------------------------------------
// Kernel 1 (unchanged from R8; ~42us, near MUFU floor): one block per row.
// ---------------------------------------------------------------------------
__global__ __launch_bounds__(256, 6) void k_feats(const float* __restrict__ adj,
                                                  const float* __restrict__ wm) {
    const int i = blockIdx.x, tid = threadIdx.x;
    const int warp = tid >> 5, lane = tid & 31;

    __shared__ float s_w [ORD * PTS];
    __shared__ float s_ws[ORD * PTS];
    __shared__ float red[ORD][8][PTS];

    if (tid < ORD * PTS) {
        float w = wm[tid];
        s_w[tid]  = w;
        s_ws[tid] = w * 0.15915494309189535f;
    }
    __syncthreads();

    const float* base = adj + (size_t)i * NN;
#pragma unroll
    for (int o = 0; o < ORD; o++) {
        const float4* row = reinterpret_cast<const float4*>(base + (size_t)o * NN * NN);
        const float4 c0 = row[tid];
        const float4 c1 = row[tid + 256];
        const float xs[8] = {c0.x, c0.y, c0.z, c0.w, c1.x, c1.y, c1.z, c1.w};

#pragma unroll
        for (int s = 0; s < 2; s++) {
            float w[7], acc[8];
#pragma unroll
            for (int q = 0; q < 7; q++) { w[q] = s_w[o * PTS + s * 8 + q]; acc[q] = 0.f; }
            const float wsp = s_ws[o * PTS + s * 8 + 7];
            acc[7] = 0.f;

#pragma unroll
            for (int e = 0; e < 8; e++) {
                const float x = xs[e];
#pragma unroll
                for (int q = 0; q < 7; q++) acc[q] += __cosf(w[q] * x);
                acc[7] += cos2pi(wsp * x);
            }

#pragma unroll
            for (int st = 0; st < 3; st++) {
                const int bit = 1 << st, half = 8 >> (st + 1);
                const bool hi = lane & bit;
#pragma unroll
                for (int q = 0; q < 4; q++) {
                    if (q < half) {
                        float send = hi ? acc[q] : acc[q + half];
                        float recv = __shfl_xor_sync(0xffffffffu, send, bit);
                        acc[q] = (hi ? acc[q + half] : acc[q]) + recv;
                    }
                }
            }
            float v = acc[0];
            v += __shfl_xor_sync(0xffffffffu, v, 8);
            v += __shfl_xor_sync(0xffffffffu, v, 16);
            if (lane < 8) red[o][warp][s * 8 + lane] = v;
        }
    }
    __syncthreads();

    if (tid < ORD * PTS) {
        const int o = tid >> 4, l = tid & 15;
        float s = 0.f;
#pragma unroll
        for (int wz = 0; wz < 8; wz++) s += red[o][wz][l];
        g_ms[(size_t)i * (ORD * PTS) + o * PTS + (l & 8) + bitrev3(l & 7)]
            = s * (1.0f / NN);
    }
}

// ---------------------------------------------------------------------------
// Kernel 2 (rebuilt): warp-per-row MLP + pooling; no block barriers in the
// compute path. 128 blocks x 512 thr (16 warps): row = bid*16 + warp.
// ---------------------------------------------------------------------------
__global__ __launch_bounds__(512) void k_tail(
    const float* __restrict__ w1, const float* __restrict__ b1,
    const float* __restrict__ w2, const float* __restrict__ b2,
    const float* __restrict__ p1, const float* __restrict__ pb1,
    const float* __restrict__ p2, const float* __restrict__ pb2,
    const float* __restrict__ cw, const float* __restrict__ cb,
    float* __restrict__ out) {

    const int tid = threadIdx.x;
    const int lane = tid & 31, warp = tid >> 5;

    __shared__ float s_w1[48 * DIM1];
    __shared__ float s_w2[DIM1 * DIM2];
    __shared__ float s_p1[DIM2 * PL1];
    __shared__ float s_p2[PL1 * PL2];
    __shared__ float s_b1[DIM1], s_b2[DIM2], s_pb1[PL1], s_pb2[PL2];
    __shared__ float wms[16][48];
    __shared__ float wh1[16][DIM1];
    __shared__ float wh2[16][DIM2];
    __shared__ float wab[16][PL1];
    __shared__ unsigned s_last;

    for (int k = tid; k < 48 * DIM1;   k += 512) s_w1[k] = w1[k];
    for (int k = tid; k < DIM1 * DIM2; k += 512) s_w2[k] = w2[k];
    for (int k = tid; k < DIM2 * PL1;  k += 512) s_p1[k] = p1[k];
    for (int k = tid; k < PL1 * PL2;   k += 512) s_p2[k] = p2[k];
    if (tid < DIM1) s_b1[tid] = b1[tid];
    if (tid < DIM2) s_b2[tid] = b2[tid];
    if (tid < PL1)  s_pb1[tid] = pb1[tid];
    if (tid < PL2)  s_pb2[tid] = pb2[tid];
    __syncthreads();

    const int r = blockIdx.x * 16 + warp;

    // load ms for this row (lane<16: 3 values each)
    if (lane < 16) {
        wms[warp][lane]      = g_ms[(size_t)r * 48 + lane];
        wms[warp][lane + 16] = g_ms[(size_t)r * 48 + lane + 16];
        wms[warp][lane + 32] = g_ms[(size_t)r * 48 + lane + 32];
    }
    __syncwarp();

    // h1: 2 outputs per lane (d = lane, lane+32), interleaved chains
    {
        float a0 = s_b1[lane], a1 = s_b1[lane + 32];
#pragma unroll
        for (int k = 0; k < 48; k++) {
            const float m = wms[warp][k];
            a0 = fmaf(m, s_w1[k * DIM1 + lane], a0);
            a1 = fmaf(m, s_w1[k * DIM1 + lane + 32], a1);
        }
        wh1[warp][lane]      = fmaxf(a0, 0.f);
        wh1[warp][lane + 32] = fmaxf(a1, 0.f);
    }
    __syncwarp();

    // h2: 1 output per lane; 2 partial accumulators
    {
        float a0 = s_b2[lane], a1 = 0.f;
#pragma unroll
        for (int k = 0; k < DIM1; k += 2) {
            a0 = fmaf(wh1[warp][k],     s_w2[k * DIM2 + lane],       a0);
            a1 = fmaf(wh1[warp][k + 1], s_w2[(k + 1) * DIM2 + lane], a1);
        }
        wh2[warp][lane] = fmaxf(a0 + a1, 0.f);
    }
    __syncwarp();

    // abstract: 1 output per lane
    {
        float a0 = s_pb1[lane], a1 = 0.f;
#pragma unroll
        for (int k = 0; k < DIM2; k += 2) {
            a0 = fmaf(wh2[warp][k],     s_p1[k * PL1 + lane],       a0);
            a1 = fmaf(wh2[warp][k + 1], s_p1[(k + 1) * PL1 + lane], a1);
        }
        wab[warp][lane] = fast_tanh(a0 + a1);
    }
    __syncwarp();

    // attention logits + exp on lanes 0..7
    float e = 0.f;
    if (lane < PL2) {
        float a0 = s_pb2[lane], a1 = 0.f;
#pragma unroll
        for (int k = 0; k < PL1; k += 2) {
            a0 = fmaf(wab[warp][k],     s_p2[k * PL2 + lane],       a0);
            a1 = fmaf(wab[warp][k + 1], s_p2[(k + 1) * PL2 + lane], a1);
        }
        e = __expf(a0 + a1);     // |s| small: safe unshifted
    }
    __syncwarp();

    // pooling: broadcast e[c], every lane adds its d-column; 32-way spread
    const float hv = wh2[warp][lane];
#pragma unroll
    for (int c = 0; c < PL2; c++) {
        float ec = __shfl_sync(0xffffffffu, e, c);
        atomicAdd(&g_num[c * DIM2 + lane], ec * hv);
    }
    if (lane < PL2) atomicAdd(&g_den[lane], e);

    // ---- last block computes the head ----
    __threadfence();
    __syncthreads();
    if (tid == 0) s_last = (atomicAdd(&g_cnt, 1u) == TGRID - 1u) ? 1u : 0u;
    __syncthreads();
    if (!s_last) return;

    __shared__ float part[8][LBL];
    if (tid < PL2 * DIM2) {
        float v = __ldcg(&g_num[tid]) / __ldcg(&g_den[tid >> 5]);
        float p[LBL];
#pragma unroll
        for (int l = 0; l < LBL; l++) p[l] = v * __ldg(cw + tid * LBL + l);
#pragma unroll
        for (int ofs = 16; ofs; ofs >>= 1)
#pragma unroll
            for (int l = 0; l < LBL; l++)
                p[l] += __shfl_xor_sync(0xffffffffu, p[l], ofs);
        if (lane == 0) {
#pragma unroll
            for (int l = 0; l < LBL; l++) part[warp][l] = p[l];
        }
    }
    __syncthreads();

    if (tid < 32) {
        float logit = -1e30f;
        if (tid < LBL) {
            float a = __ldg(cb + tid);
#pragma unroll
            for (int wz = 0; wz < 8; wz++) a += part[wz][tid];
            logit = a;
        }
        float m2 = logit;
#pragma unroll
        for (int ofs = 16; ofs; ofs >>= 1)
            m2 = fmaxf(m2, __shfl_xor_sync(0xffffffffu, m2, ofs));
        float ex = (tid < LBL) ? expf(logit - m2) : 0.f;
        float s2 = ex;
#pragma unroll
        for (int ofs = 16; ofs; ofs >>= 1)
            s2 += __shfl_xor_sync(0xffffffffu, s2, ofs);
        if (tid < LBL) out[tid] = logit - m2 - logf(s2);
    }
    __syncthreads();

    // reset for next graph replay
    if (tid < PL2 * DIM2) __stcg(&g_num[tid], 0.f);
    if (tid < PL2) __stcg(&g_den[tid], 0.f);
    if (tid == 0) { __threadfence(); atomicExch(&g_cnt, 0u); }
}

// ---------------------------------------------------------------------------
extern "C" void kernel_launch(void* const* d_in, const int* in_sizes, int n_in,
                              void* d_out, int out_size) {
    const float* adj = (const float*)d_in[0];
    const float* wm  = (const float*)d_in[1];
    const float* w1  = (const float*)d_in[2];
    const float* b1  = (const float*)d_in[3];
    const float* w2  = (const float*)d_in[4];
    const float* b2  = (const float*)d_in[5];
    const float* p1  = (const float*)d_in[6];
    const float* pb1 = (const float*)d_in[7];
    const float* p2  = (const float*)d_in[8];
    const float* pb2 = (const float*)d_in[9];
    const float* cw  = (const float*)d_in[10];
    const float* cb  = (const float*)d_in[11];
    float* out = (float*)d_out;

    k_feats<<<NN, 256>>>(adj, wm);
    k_tail <<<TGRID, 512>>>(w1, b1, w2, b2, p1, pb1, p2, pb2, cw, cb, out);
}

// round 10
// speedup vs baseline: 1.2161x; 1.2161x over previous
#include <cuda_runtime.h>

#define NN   2048
#define ORD  3
#define PTS  16
#define DIM1 64
#define DIM2 32
#define PL1  32
#define PL2  8
#define LBL  10
#define TGRID 128               // k_tail blocks; 16 warps = 16 rows each

// Scratch (no allocations allowed)
__device__ float    g_ms[NN * ORD * PTS];   // [n, 48]
__device__ float    g_num[PL2 * DIM2];
__device__ float    g_den[PL2];
__device__ unsigned g_cnt;

__device__ __forceinline__ float fast_tanh(float x) {
    float r;
    asm("tanh.approx.f32 %0, %1;" : "=f"(r) : "f"(x));
    return r;
}

// cos(2*pi*y): exact reduction + even poly through (2*pi*t)^14, max err ~4e-6
__device__ __forceinline__ float cos2pi(float y) {
    float t = y - rintf(y);
    float u = t * t;
    float p = -1.7143907f;
    p = fmaf(p, u,  7.9035539f);
    p = fmaf(p, u, -26.4257337f);
    p = fmaf(p, u,  60.2446418f);
    p = fmaf(p, u, -85.4567987f);
    p = fmaf(p, u,  64.9393940f);
    p = fmaf(p, u, -19.7392088f);
    p = fmaf(p, u,  1.0f);
    return p;
}

__device__ __forceinline__ int bitrev3(int x) {
    return ((x & 1) << 2) | (x & 2) | ((x & 4) >> 2);
}

// ---------------------------------------------------------------------------
// Kernel 1 (unchanged; ~42us, near MUFU floor): one block per row.
// ---------------------------------------------------------------------------
__global__ __launch_bounds__(256, 6) void k_feats(const float* __restrict__ adj,
                                                  const float* __restrict__ wm) {
    const int i = blockIdx.x, tid = threadIdx.x;
    const int warp = tid >> 5, lane = tid & 31;

    __shared__ float s_w [ORD * PTS];
    __shared__ float s_ws[ORD * PTS];
    __shared__ float red[ORD][8][PTS];

    if (tid < ORD * PTS) {
        float w = wm[tid];
        s_w[tid]  = w;
        s_ws[tid] = w * 0.15915494309189535f;
    }
    __syncthreads();

    const float* base = adj + (size_t)i * NN;
#pragma unroll
    for (int o = 0; o < ORD; o++) {
        const float4* row = reinterpret_cast<const float4*>(base + (size_t)o * NN * NN);
        const float4 c0 = row[tid];
        const float4 c1 = row[tid + 256];
        const float xs[8] = {c0.x, c0.y, c0.z, c0.w, c1.x, c1.y, c1.z, c1.w};

#pragma unroll
        for (int s = 0; s < 2; s++) {
            float w[7], acc[8];
#pragma unroll
            for (int q = 0; q < 7; q++) { w[q] = s_w[o * PTS + s * 8 + q]; acc[q] = 0.f; }
            const float wsp = s_ws[o * PTS + s * 8 + 7];
            acc[7] = 0.f;

#pragma unroll
            for (int e = 0; e < 8; e++) {
                const float x = xs[e];
#pragma unroll
                for (int q = 0; q < 7; q++) acc[q] += __cosf(w[q] * x);
                acc[7] += cos2pi(wsp * x);
            }

#pragma unroll
            for (int st = 0; st < 3; st++) {
                const int bit = 1 << st, half = 8 >> (st + 1);
                const bool hi = lane & bit;
#pragma unroll
                for (int q = 0; q < 4; q++) {
                    if (q < half) {
                        float send = hi ? acc[q] : acc[q + half];
                        float recv = __shfl_xor_sync(0xffffffffu, send, bit);
                        acc[q] = (hi ? acc[q + half] : acc[q]) + recv;
                    }
                }
            }
            float v = acc[0];
            v += __shfl_xor_sync(0xffffffffu, v, 8);
            v += __shfl_xor_sync(0xffffffffu, v, 16);
            if (lane < 8) red[o][warp][s * 8 + lane] = v;
        }
    }
    __syncthreads();

    if (tid < ORD * PTS) {
        const int o = tid >> 4, l = tid & 15;
        float s = 0.f;
#pragma unroll
        for (int wz = 0; wz < 8; wz++) s += red[o][wz][l];
        g_ms[(size_t)i * (ORD * PTS) + o * PTS + (l & 8) + bitrev3(l & 7)]
            = s * (1.0f / NN);
    }
}

// ---------------------------------------------------------------------------
// Kernel 2: warp-per-row MLP, then BLOCK pre-reduction of the pooling outer
// product before a single global atomicAdd per thread (128 adds/address).
// ---------------------------------------------------------------------------
__global__ __launch_bounds__(512) void k_tail(
    const float* __restrict__ w1, const float* __restrict__ b1,
    const float* __restrict__ w2, const float* __restrict__ b2,
    const float* __restrict__ p1, const float* __restrict__ pb1,
    const float* __restrict__ p2, const float* __restrict__ pb2,
    const float* __restrict__ cw, const float* __restrict__ cb,
    float* __restrict__ out) {

    const int tid = threadIdx.x;
    const int lane = tid & 31, warp = tid >> 5;

    __shared__ float s_w1[48 * DIM1];
    __shared__ float s_w2[DIM1 * DIM2];
    __shared__ float s_p1[DIM2 * PL1];
    __shared__ float s_p2[PL1 * PL2];
    __shared__ float s_b1[DIM1], s_b2[DIM2], s_pb1[PL1], s_pb2[PL2];
    __shared__ float wms[16][48];
    __shared__ float wh1[16][DIM1];
    __shared__ float wh2[16][DIM2];
    __shared__ float wab[16][PL1];
    __shared__ float we [16][PL2];
    __shared__ unsigned s_last;

    for (int k = tid; k < 48 * DIM1;   k += 512) s_w1[k] = w1[k];
    for (int k = tid; k < DIM1 * DIM2; k += 512) s_w2[k] = w2[k];
    for (int k = tid; k < DIM2 * PL1;  k += 512) s_p1[k] = p1[k];
    for (int k = tid; k < PL1 * PL2;   k += 512) s_p2[k] = p2[k];
    if (tid < DIM1) s_b1[tid] = b1[tid];
    if (tid < DIM2) s_b2[tid] = b2[tid];
    if (tid < PL1)  s_pb1[tid] = pb1[tid];
    if (tid < PL2)  s_pb2[tid] = pb2[tid];
    __syncthreads();

    const int r = blockIdx.x * 16 + warp;

    // load ms for this row
    if (lane < 16) {
        wms[warp][lane]      = g_ms[(size_t)r * 48 + lane];
        wms[warp][lane + 16] = g_ms[(size_t)r * 48 + lane + 16];
        wms[warp][lane + 32] = g_ms[(size_t)r * 48 + lane + 32];
    }
    __syncwarp();

    // h1: 2 outputs per lane
    {
        float a0 = s_b1[lane], a1 = s_b1[lane + 32];
#pragma unroll
        for (int k = 0; k < 48; k++) {
            const float m = wms[warp][k];
            a0 = fmaf(m, s_w1[k * DIM1 + lane], a0);
            a1 = fmaf(m, s_w1[k * DIM1 + lane + 32], a1);
        }
        wh1[warp][lane]      = fmaxf(a0, 0.f);
        wh1[warp][lane + 32] = fmaxf(a1, 0.f);
    }
    __syncwarp();

    // h2: 1 output per lane
    {
        float a0 = s_b2[lane], a1 = 0.f;
#pragma unroll
        for (int k = 0; k < DIM1; k += 2) {
            a0 = fmaf(wh1[warp][k],     s_w2[k * DIM2 + lane],       a0);
            a1 = fmaf(wh1[warp][k + 1], s_w2[(k + 1) * DIM2 + lane], a1);
        }
        wh2[warp][lane] = fmaxf(a0 + a1, 0.f);
    }
    __syncwarp();

    // abstract: 1 output per lane
    {
        float a0 = s_pb1[lane], a1 = 0.f;
#pragma unroll
        for (int k = 0; k < DIM2; k += 2) {
            a0 = fmaf(wh2[warp][k],     s_p1[k * PL1 + lane],       a0);
            a1 = fmaf(wh2[warp][k + 1], s_p1[(k + 1) * PL1 + lane], a1);
        }
        wab[warp][lane] = fast_tanh(a0 + a1);
    }
    __syncwarp();

    // attention logits + exp on lanes 0..7
    if (lane < PL2) {
        float a0 = s_pb2[lane], a1 = 0.f;
#pragma unroll
        for (int k = 0; k < PL1; k += 2) {
            a0 = fmaf(wab[warp][k],     s_p2[k * PL2 + lane],       a0);
            a1 = fmaf(wab[warp][k + 1], s_p2[(k + 1) * PL2 + lane], a1);
        }
        we[warp][lane] = __expf(a0 + a1);   // |s| small: safe unshifted
    }
    __syncthreads();

    // block pre-reduction: thread (c,d) = tid<256 sums over the 16 rows
    if (tid < PL2 * DIM2) {
        const int c = tid >> 5, d = tid & 31;
        float num = 0.f, den = 0.f;
#pragma unroll
        for (int rr = 0; rr < 16; rr++) {
            const float e = we[rr][c];
            num = fmaf(e, wh2[rr][d], num);
            if (d == 0) den += e;
        }
        atomicAdd(&g_num[tid], num);
        if (d == 0) atomicAdd(&g_den[c], den);
    }

    // ---- last block computes the head ----
    __threadfence();
    __syncthreads();
    if (tid == 0) s_last = (atomicAdd(&g_cnt, 1u) == TGRID - 1u) ? 1u : 0u;
    __syncthreads();
    if (!s_last) return;

    __shared__ float part[8][LBL];
    if (tid < PL2 * DIM2) {
        float v = __ldcg(&g_num[tid]) / __ldcg(&g_den[tid >> 5]);
        float p[LBL];
#pragma unroll
        for (int l = 0; l < LBL; l++) p[l] = v * __ldg(cw + tid * LBL + l);
#pragma unroll
        for (int ofs = 16; ofs; ofs >>= 1)
#pragma unroll
            for (int l = 0; l < LBL; l++)
                p[l] += __shfl_xor_sync(0xffffffffu, p[l], ofs);
        if (lane == 0) {
#pragma unroll
            for (int l = 0; l < LBL; l++) part[warp][l] = p[l];
        }
    }
    __syncthreads();

    if (tid < 32) {
        float logit = -1e30f;
        if (tid < LBL) {
            float a = __ldg(cb + tid);
#pragma unroll
            for (int wz = 0; wz < 8; wz++) a += part[wz][tid];
            logit = a;
        }
        float m2 = logit;
#pragma unroll
        for (int ofs = 16; ofs; ofs >>= 1)
            m2 = fmaxf(m2, __shfl_xor_sync(0xffffffffu, m2, ofs));
        float ex = (tid < LBL) ? expf(logit - m2) : 0.f;
        float s2 = ex;
#pragma unroll
        for (int ofs = 16; ofs; ofs >>= 1)
            s2 += __shfl_xor_sync(0xffffffffu, s2, ofs);
        if (tid < LBL) out[tid] = logit - m2 - logf(s2);
    }
    __syncthreads();

    // reset for next graph replay
    if (tid < PL2 * DIM2) __stcg(&g_num[tid], 0.f);
    if (tid < PL2) __stcg(&g_den[tid], 0.f);
    if (tid == 0) { __threadfence(); atomicExch(&g_cnt, 0u); }
}

// ---------------------------------------------------------------------------
extern "C" void kernel_launch(void* const* d_in, const int* in_sizes, int n_in,
                              void* d_out, int out_size) {
    const float* adj = (const float*)d_in[0];
    const float* wm  = (const float*)d_in[1];
    const float* w1  = (const float*)d_in[2];
    const float* b1  = (const float*)d_in[3];
    const float* w2  = (const float*)d_in[4];
    const float* b2  = (const float*)d_in[5];
    const float* p1  = (const float*)d_in[6];
    const float* pb1 = (const float*)d_in[7];
    const float* p2  = (const float*)d_in[8];
    const float* pb2 = (const float*)d_in[9];
    const float* cw  = (const float*)d_in[10];
    const float* cb  = (const float*)d_in[11];
    float* out = (float*)d_out;

    k_feats<<<NN, 256>>>(adj, wm);
    k_tail <<<TGRID, 512>>>(w1, b1, w2, b2, p1, pb1, p2, pb2, cw, cb, out);
}

// round 11
// speedup vs baseline: 1.2331x; 1.0140x over previous
#include <cuda_runtime.h>

#define NN   2048
#define ORD  3
#define PTS  16
#define DIM1 64
#define DIM2 32
#define PL1  32
#define PL2  8
#define LBL  10
#define TGRID 256               // k_tail blocks; 8 warps = 8 rows each

// Scratch (no allocations allowed)
__device__ float    g_ms[NN * ORD * PTS];   // [n, 48]
__device__ float    g_num[PL2 * DIM2];
__device__ float    g_den[PL2];
__device__ unsigned g_cnt;

__device__ __forceinline__ float fast_tanh(float x) {
    float r;
    asm("tanh.approx.f32 %0, %1;" : "=f"(r) : "f"(x));
    return r;
}

// cos(2*pi*y): exact reduction + even poly through (2*pi*t)^14, max err ~4e-6
__device__ __forceinline__ float cos2pi(float y) {
    float t = y - rintf(y);
    float u = t * t;
    float p = -1.7143907f;
    p = fmaf(p, u,  7.9035539f);
    p = fmaf(p, u, -26.4257337f);
    p = fmaf(p, u,  60.2446418f);
    p = fmaf(p, u, -85.4567987f);
    p = fmaf(p, u,  64.9393940f);
    p = fmaf(p, u, -19.7392088f);
    p = fmaf(p, u,  1.0f);
    return p;
}

__device__ __forceinline__ int bitrev3(int x) {
    return ((x & 1) << 2) | (x & 2) | ((x & 4) >> 2);
}

// ---------------------------------------------------------------------------
// Kernel 1 (unchanged; ~43us, near MUFU floor): one block per row.
// ---------------------------------------------------------------------------
__global__ __launch_bounds__(256, 6) void k_feats(const float* __restrict__ adj,
                                                  const float* __restrict__ wm) {
    const int i = blockIdx.x, tid = threadIdx.x;
    const int warp = tid >> 5, lane = tid & 31;

    __shared__ float s_w [ORD * PTS];
    __shared__ float s_ws[ORD * PTS];
    __shared__ float red[ORD][8][PTS];

    if (tid < ORD * PTS) {
        float w = wm[tid];
        s_w[tid]  = w;
        s_ws[tid] = w * 0.15915494309189535f;
    }
    __syncthreads();

    const float* base = adj + (size_t)i * NN;
#pragma unroll
    for (int o = 0; o < ORD; o++) {
        const float4* row = reinterpret_cast<const float4*>(base + (size_t)o * NN * NN);
        const float4 c0 = row[tid];
        const float4 c1 = row[tid + 256];
        const float xs[8] = {c0.x, c0.y, c0.z, c0.w, c1.x, c1.y, c1.z, c1.w};

#pragma unroll
        for (int s = 0; s < 2; s++) {
            float w[7], acc[8];
#pragma unroll
            for (int q = 0; q < 7; q++) { w[q] = s_w[o * PTS + s * 8 + q]; acc[q] = 0.f; }
            const float wsp = s_ws[o * PTS + s * 8 + 7];
            acc[7] = 0.f;

#pragma unroll
            for (int e = 0; e < 8; e++) {
                const float x = xs[e];
#pragma unroll
                for (int q = 0; q < 7; q++) acc[q] += __cosf(w[q] * x);
                acc[7] += cos2pi(wsp * x);
            }

#pragma unroll
            for (int st = 0; st < 3; st++) {
                const int bit = 1 << st, half = 8 >> (st + 1);
                const bool hi = lane & bit;
#pragma unroll
                for (int q = 0; q < 4; q++) {
                    if (q < half) {
                        float send = hi ? acc[q] : acc[q + half];
                        float recv = __shfl_xor_sync(0xffffffffu, send, bit);
                        acc[q] = (hi ? acc[q + half] : acc[q]) + recv;
                    }
                }
            }
            float v = acc[0];
            v += __shfl_xor_sync(0xffffffffu, v, 8);
            v += __shfl_xor_sync(0xffffffffu, v, 16);
            if (lane < 8) red[o][warp][s * 8 + lane] = v;
        }
    }
    __syncthreads();

    if (tid < ORD * PTS) {
        const int o = tid >> 4, l = tid & 15;
        float s = 0.f;
#pragma unroll
        for (int wz = 0; wz < 8; wz++) s += red[o][wz][l];
        g_ms[(size_t)i * (ORD * PTS) + o * PTS + (l & 8) + bitrev3(l & 7)]
            = s * (1.0f / NN);
    }
}

// ---------------------------------------------------------------------------
// Kernel 2: warp-per-row MLP with direct L1-served weight loads (no staging,
// no staging barrier), 4-way partial accumulators, one pre-reduction barrier,
// one atomicAdd per thread. Last block computes the head.
// ---------------------------------------------------------------------------
__global__ __launch_bounds__(256) void k_tail(
    const float* __restrict__ w1, const float* __restrict__ b1,
    const float* __restrict__ w2, const float* __restrict__ b2,
    const float* __restrict__ p1, const float* __restrict__ pb1,
    const float* __restrict__ p2, const float* __restrict__ pb2,
    const float* __restrict__ cw, const float* __restrict__ cb,
    float* __restrict__ out) {

    const int tid = threadIdx.x;
    const int lane = tid & 31, warp = tid >> 5;

    __shared__ float wms[8][48];
    __shared__ float wh1[8][DIM1];
    __shared__ float wh2[8][DIM2];
    __shared__ float wab[8][PL1];
    __shared__ float we [8][PL2];
    __shared__ unsigned s_last;

    const int r = blockIdx.x * 8 + warp;

    // load ms for this row (lane<16: 3 values each)
    if (lane < 16) {
        wms[warp][lane]      = g_ms[(size_t)r * 48 + lane];
        wms[warp][lane + 16] = g_ms[(size_t)r * 48 + lane + 16];
        wms[warp][lane + 32] = g_ms[(size_t)r * 48 + lane + 32];
    }
    __syncwarp();

    // h1: 2 outputs per lane (d = lane, lane+32), 4 partials each
    {
        float a0 = __ldg(b1 + lane), a1 = 0.f, a2 = 0.f, a3 = 0.f;
        float c0 = __ldg(b1 + lane + 32), c1 = 0.f, c2 = 0.f, c3 = 0.f;
#pragma unroll
        for (int k = 0; k < 48; k += 4) {
            const float m0 = wms[warp][k],     m1 = wms[warp][k + 1];
            const float m2 = wms[warp][k + 2], m3 = wms[warp][k + 3];
            a0 = fmaf(m0, __ldg(w1 + (k    ) * DIM1 + lane), a0);
            a1 = fmaf(m1, __ldg(w1 + (k + 1) * DIM1 + lane), a1);
            a2 = fmaf(m2, __ldg(w1 + (k + 2) * DIM1 + lane), a2);
            a3 = fmaf(m3, __ldg(w1 + (k + 3) * DIM1 + lane), a3);
            c0 = fmaf(m0, __ldg(w1 + (k    ) * DIM1 + lane + 32), c0);
            c1 = fmaf(m1, __ldg(w1 + (k + 1) * DIM1 + lane + 32), c1);
            c2 = fmaf(m2, __ldg(w1 + (k + 2) * DIM1 + lane + 32), c2);
            c3 = fmaf(m3, __ldg(w1 + (k + 3) * DIM1 + lane + 32), c3);
        }
        wh1[warp][lane]      = fmaxf((a0 + a1) + (a2 + a3), 0.f);
        wh1[warp][lane + 32] = fmaxf((c0 + c1) + (c2 + c3), 0.f);
    }
    __syncwarp();

    // h2: 1 output per lane, 4 partials
    {
        float a0 = __ldg(b2 + lane), a1 = 0.f, a2 = 0.f, a3 = 0.f;
#pragma unroll
        for (int k = 0; k < DIM1; k += 4) {
            a0 = fmaf(wh1[warp][k],     __ldg(w2 + (k    ) * DIM2 + lane), a0);
            a1 = fmaf(wh1[warp][k + 1], __ldg(w2 + (k + 1) * DIM2 + lane), a1);
            a2 = fmaf(wh1[warp][k + 2], __ldg(w2 + (k + 2) * DIM2 + lane), a2);
            a3 = fmaf(wh1[warp][k + 3], __ldg(w2 + (k + 3) * DIM2 + lane), a3);
        }
        wh2[warp][lane] = fmaxf((a0 + a1) + (a2 + a3), 0.f);
    }
    __syncwarp();

    // abstract: 1 output per lane, 4 partials
    {
        float a0 = __ldg(pb1 + lane), a1 = 0.f, a2 = 0.f, a3 = 0.f;
#pragma unroll
        for (int k = 0; k < DIM2; k += 4) {
            a0 = fmaf(wh2[warp][k],     __ldg(p1 + (k    ) * PL1 + lane), a0);
            a1 = fmaf(wh2[warp][k + 1], __ldg(p1 + (k + 1) * PL1 + lane), a1);
            a2 = fmaf(wh2[warp][k + 2], __ldg(p1 + (k + 2) * PL1 + lane), a2);
            a3 = fmaf(wh2[warp][k + 3], __ldg(p1 + (k + 3) * PL1 + lane), a3);
        }
        wab[warp][lane] = fast_tanh((a0 + a1) + (a2 + a3));
    }
    __syncwarp();

    // attention logits + exp on lanes 0..7 (4 partials)
    if (lane < PL2) {
        float a0 = __ldg(pb2 + lane), a1 = 0.f, a2 = 0.f, a3 = 0.f;
#pragma unroll
        for (int k = 0; k < PL1; k += 4) {
            a0 = fmaf(wab[warp][k],     __ldg(p2 + (k    ) * PL2 + lane), a0);
            a1 = fmaf(wab[warp][k + 1], __ldg(p2 + (k + 1) * PL2 + lane), a1);
            a2 = fmaf(wab[warp][k + 2], __ldg(p2 + (k + 2) * PL2 + lane), a2);
            a3 = fmaf(wab[warp][k + 3], __ldg(p2 + (k + 3) * PL2 + lane), a3);
        }
        we[warp][lane] = __expf((a0 + a1) + (a2 + a3));  // |s| small: safe unshifted
    }
    __syncthreads();

    // block pre-reduction: thread (c,d) sums the 8 rows, single atomic
    {
        const int c = tid >> 5, d = tid & 31;
        float num = 0.f, den = 0.f;
#pragma unroll
        for (int rr = 0; rr < 8; rr++) {
            const float e = we[rr][c];
            num = fmaf(e, wh2[rr][d], num);
            if (d == 0) den += e;
        }
        atomicAdd(&g_num[tid], num);
        if (d == 0) atomicAdd(&g_den[c], den);
    }

    // ---- last block computes the head ----
    __threadfence();
    __syncthreads();
    if (tid == 0) s_last = (atomicAdd(&g_cnt, 1u) == TGRID - 1u) ? 1u : 0u;
    __syncthreads();
    if (!s_last) return;

    __shared__ float part[8][LBL];
    {
        float v = __ldcg(&g_num[tid]) / __ldcg(&g_den[tid >> 5]);
        float p[LBL];
#pragma unroll
        for (int l = 0; l < LBL; l++) p[l] = v * __ldg(cw + tid * LBL + l);
#pragma unroll
        for (int ofs = 16; ofs; ofs >>= 1)
#pragma unroll
            for (int l = 0; l < LBL; l++)
                p[l] += __shfl_xor_sync(0xffffffffu, p[l], ofs);
        if (lane == 0) {
#pragma unroll
            for (int l = 0; l < LBL; l++) part[warp][l] = p[l];
        }
    }
    __syncthreads();

    if (tid < 32) {
        float logit = -1e30f;
        if (tid < LBL) {
            float a = __ldg(cb + tid);
#pragma unroll
            for (int wz = 0; wz < 8; wz++) a += part[wz][tid];
            logit = a;
        }
        float m2 = logit;
#pragma unroll
        for (int ofs = 16; ofs; ofs >>= 1)
            m2 = fmaxf(m2, __shfl_xor_sync(0xffffffffu, m2, ofs));
        float ex = (tid < LBL) ? expf(logit - m2) : 0.f;
        float s2 = ex;
#pragma unroll
        for (int ofs = 16; ofs; ofs >>= 1)
            s2 += __shfl_xor_sync(0xffffffffu, s2, ofs);
        if (tid < LBL) out[tid] = logit - m2 - logf(s2);
    }
    __syncthreads();

    // reset for next graph replay
    __stcg(&g_num[tid], 0.f);
    if (tid < PL2) __stcg(&g_den[tid], 0.f);
    if (tid == 0) { __threadfence(); atomicExch(&g_cnt, 0u); }
}

// ---------------------------------------------------------------------------
extern "C" void kernel_launch(void* const* d_in, const int* in_sizes, int n_in,
                              void* d_out, int out_size) {
    const float* adj = (const float*)d_in[0];
    const float* wm  = (const float*)d_in[1];
    const float* w1  = (const float*)d_in[2];
    const float* b1  = (const float*)d_in[3];
    const float* w2  = (const float*)d_in[4];
    const float* b2  = (const float*)d_in[5];
    const float* p1  = (const float*)d_in[6];
    const float* pb1 = (const float*)d_in[7];
    const float* p2  = (const float*)d_in[8];
    const float* pb2 = (const float*)d_in[9];
    const float* cw  = (const float*)d_in[10];
    const float* cb  = (const float*)d_in[11];
    float* out = (float*)d_out;

    k_feats<<<NN, 256>>>(adj, wm);
    k_tail <<<TGRID, 256>>>(w1, b1, w2, b2, p1, pb1, p2, pb2, cw, cb, out);
}

// round 12
// speedup vs baseline: 1.2408x; 1.0062x over previous
#include <cuda_runtime.h>

#define NN   2048
#define ORD  3
#define PTS  16
#define DIM1 64
#define DIM2 32
#define PL1  32
#define PL2  8
#define LBL  10
#define GRID (NN / 2)           // 1024 blocks, 2 rows each

// Scratch accumulators (zero at module load; self-reset each launch)
__device__ float    g_num[PL2 * DIM2];
__device__ float    g_den[PL2];
__device__ unsigned g_cnt;

__device__ __forceinline__ float fast_tanh(float x) {
    float r;
    asm("tanh.approx.f32 %0, %1;" : "=f"(r) : "f"(x));
    return r;
}

// cos(2*pi*y): exact reduction + even poly through (2*pi*t)^14, max err ~4e-6
__device__ __forceinline__ float cos2pi(float y) {
    float t = y - rintf(y);
    float u = t * t;
    float p = -1.7143907f;
    p = fmaf(p, u,  7.9035539f);
    p = fmaf(p, u, -26.4257337f);
    p = fmaf(p, u,  60.2446418f);
    p = fmaf(p, u, -85.4567987f);
    p = fmaf(p, u,  64.9393940f);
    p = fmaf(p, u, -19.7392088f);
    p = fmaf(p, u,  1.0f);
    return p;
}

__device__ __forceinline__ int bitrev3(int x) {
    return ((x & 1) << 2) | (x & 2) | ((x & 4) >> 2);
}

// ---------------------------------------------------------------------------
// Fused kernel, 2 rows per block: warps 0-3 -> row 2*bid, warps 4-7 -> 2*bid+1.
// Per row-group (128 thr): 16 elems/thread held in registers; two 8-point
// sweeps per order, each sweep = 6 MUFU points + 2 FMA-poly points.
// Tail (MLP+pool) runs once per 2 rows at 2x width. Last block does the head.
// ---------------------------------------------------------------------------
__global__ __launch_bounds__(256, 5) void k_fused(
    const float* __restrict__ adj, const float* __restrict__ wm,
    const float* __restrict__ w1, const float* __restrict__ b1,
    const float* __restrict__ w2, const float* __restrict__ b2,
    const float* __restrict__ p1, const float* __restrict__ pb1,
    const float* __restrict__ p2, const float* __restrict__ pb2,
    const float* __restrict__ cw, const float* __restrict__ cb,
    float* __restrict__ out) {

    const int tid = threadIdx.x;
    const int warp = tid >> 5, lane = tid & 31;
    const int wg = warp >> 2;               // row group 0/1
    const int wtid = tid & 127;             // thread within row group

    __shared__ float s_w [ORD * PTS];
    __shared__ float s_ws[ORD * PTS];
    __shared__ float red[ORD][2][4][PTS];   // [order][row][warp-in-group][slot]
    __shared__ float s_ms[2][ORD * PTS];
    __shared__ float sh1[2][DIM1];
    __shared__ float sh2[2][DIM2];
    __shared__ float sab[2][PL1];
    __shared__ float se [2][PL2];           // exp(attention logits)
    __shared__ unsigned s_last;

    if (tid < ORD * PTS) {
        float w = wm[tid];
        s_w[tid]  = w;
        s_ws[tid] = w * 0.15915494309189535f;   // 1/(2*pi)
    }
    __syncthreads();

    const int r = blockIdx.x * 2 + wg;
    const float* base = adj + (size_t)r * NN;

#pragma unroll
    for (int o = 0; o < ORD; o++) {
        const float4* row = reinterpret_cast<const float4*>(base + (size_t)o * NN * NN);
        const float4 c0 = row[wtid];
        const float4 c1 = row[wtid + 128];
        const float4 c2 = row[wtid + 256];
        const float4 c3 = row[wtid + 384];
        const float xs[16] = {c0.x, c0.y, c0.z, c0.w, c1.x, c1.y, c1.z, c1.w,
                              c2.x, c2.y, c2.z, c2.w, c3.x, c3.y, c3.z, c3.w};

#pragma unroll
        for (int s = 0; s < 2; s++) {
            float w[6], acc[8];
#pragma unroll
            for (int q = 0; q < 6; q++) { w[q] = s_w[o * PTS + s * 8 + q]; acc[q] = 0.f; }
            const float wsp0 = s_ws[o * PTS + s * 8 + 6];
            const float wsp1 = s_ws[o * PTS + s * 8 + 7];
            acc[6] = 0.f; acc[7] = 0.f;

#pragma unroll
            for (int e = 0; e < 16; e++) {
                const float x = xs[e];
#pragma unroll
                for (int q = 0; q < 6; q++) acc[q] += __cosf(w[q] * x);
                acc[6] += cos2pi(wsp0 * x);
                acc[7] += cos2pi(wsp1 * x);
            }

            // split-butterfly: 8 accs -> 1 per lane (point = bitrev3(lane&7))
#pragma unroll
            for (int st = 0; st < 3; st++) {
                const int bit = 1 << st, half = 8 >> (st + 1);
                const bool hi = lane & bit;
#pragma unroll
                for (int q = 0; q < 4; q++) {
                    if (q < half) {
                        float send = hi ? acc[q] : acc[q + half];
                        float recv = __shfl_xor_sync(0xffffffffu, send, bit);
                        acc[q] = (hi ? acc[q + half] : acc[q]) + recv;
                    }
                }
            }
            float v = acc[0];
            v += __shfl_xor_sync(0xffffffffu, v, 8);
            v += __shfl_xor_sync(0xffffffffu, v, 16);
            if (lane < 8) red[o][wg][warp & 3][s * 8 + lane] = v;
        }
    }
    __syncthreads();

    // gather: 96 outputs (2 rows x 48)
    if (tid < 2 * ORD * PTS) {
        const int row = tid / 48, t = tid % 48;
        const int o = t >> 4, l = t & 15;
        float s = 0.f;
#pragma unroll
        for (int wz = 0; wz < 4; wz++) s += red[o][row][wz][l];
        s_ms[row][o * PTS + (l & 8) + bitrev3(l & 7)] = s * (1.0f / NN);
    }
    __syncthreads();

    // ---- tail: 2 rows in parallel, 4-way partial accumulators ----
    if (tid < 2 * DIM1) {                   // h1: 128 outputs
        const int row = tid >> 6, d = tid & 63;
        float a0 = __ldg(b1 + d), a1 = 0.f, a2 = 0.f, a3 = 0.f;
#pragma unroll
        for (int k = 0; k < 48; k += 4) {
            a0 = fmaf(s_ms[row][k],     __ldg(w1 + (k    ) * DIM1 + d), a0);
            a1 = fmaf(s_ms[row][k + 1], __ldg(w1 + (k + 1) * DIM1 + d), a1);
            a2 = fmaf(s_ms[row][k + 2], __ldg(w1 + (k + 2) * DIM1 + d), a2);
            a3 = fmaf(s_ms[row][k + 3], __ldg(w1 + (k + 3) * DIM1 + d), a3);
        }
        sh1[row][d] = fmaxf((a0 + a1) + (a2 + a3), 0.f);
    }
    __syncthreads();

    if (tid < 2 * DIM2) {                   // h2: 64 outputs
        const int row = tid >> 5, d = tid & 31;
        float a0 = __ldg(b2 + d), a1 = 0.f, a2 = 0.f, a3 = 0.f;
#pragma unroll
        for (int k = 0; k < DIM1; k += 4) {
            a0 = fmaf(sh1[row][k],     __ldg(w2 + (k    ) * DIM2 + d), a0);
            a1 = fmaf(sh1[row][k + 1], __ldg(w2 + (k + 1) * DIM2 + d), a1);
            a2 = fmaf(sh1[row][k + 2], __ldg(w2 + (k + 2) * DIM2 + d), a2);
            a3 = fmaf(sh1[row][k + 3], __ldg(w2 + (k + 3) * DIM2 + d), a3);
        }
        sh2[row][d] = fmaxf((a0 + a1) + (a2 + a3), 0.f);
    }
    __syncthreads();

    if (tid < 2 * PL1) {                    // abstract: 64 outputs
        const int row = tid >> 5, d = tid & 31;
        float a0 = __ldg(pb1 + d), a1 = 0.f, a2 = 0.f, a3 = 0.f;
#pragma unroll
        for (int k = 0; k < DIM2; k += 4) {
            a0 = fmaf(sh2[row][k],     __ldg(p1 + (k    ) * PL1 + d), a0);
            a1 = fmaf(sh2[row][k + 1], __ldg(p1 + (k + 1) * PL1 + d), a1);
            a2 = fmaf(sh2[row][k + 2], __ldg(p1 + (k + 2) * PL1 + d), a2);
            a3 = fmaf(sh2[row][k + 3], __ldg(p1 + (k + 3) * PL1 + d), a3);
        }
        sab[row][d] = fast_tanh((a0 + a1) + (a2 + a3));
    }
    __syncthreads();

    if (tid < 2 * PL2) {                    // attention logits -> exp
        const int row = tid >> 3, c = tid & 7;
        float a0 = __ldg(pb2 + c), a1 = 0.f, a2 = 0.f, a3 = 0.f;
#pragma unroll
        for (int k = 0; k < PL1; k += 4) {
            a0 = fmaf(sab[row][k],     __ldg(p2 + (k    ) * PL2 + c), a0);
            a1 = fmaf(sab[row][k + 1], __ldg(p2 + (k + 1) * PL2 + c), a1);
            a2 = fmaf(sab[row][k + 2], __ldg(p2 + (k + 2) * PL2 + c), a2);
            a3 = fmaf(sab[row][k + 3], __ldg(p2 + (k + 3) * PL2 + c), a3);
        }
        se[row][c] = __expf((a0 + a1) + (a2 + a3));   // |s| small: safe unshifted
    }
    __syncthreads();

    // pooling: one atomic per thread covering both rows
    {
        const int c = tid >> 5, d = tid & 31;
        const float num = se[0][c] * sh2[0][d] + se[1][c] * sh2[1][d];
        atomicAdd(&g_num[tid], num);
        if (d == 0) atomicAdd(&g_den[c], se[0][c] + se[1][c]);
    }

    // ---- last block computes the head ----
    __threadfence();
    __syncthreads();
    if (tid == 0) s_last = (atomicAdd(&g_cnt, 1u) == GRID - 1u) ? 1u : 0u;
    __syncthreads();
    if (!s_last) return;

    __shared__ float part[8][LBL];
    {
        float v = __ldcg(&g_num[tid]) / __ldcg(&g_den[tid >> 5]);
        float p[LBL];
#pragma unroll
        for (int l = 0; l < LBL; l++) p[l] = v * __ldg(cw + tid * LBL + l);
#pragma unroll
        for (int ofs = 16; ofs; ofs >>= 1)
#pragma unroll
            for (int l = 0; l < LBL; l++)
                p[l] += __shfl_xor_sync(0xffffffffu, p[l], ofs);
        if (lane == 0) {
#pragma unroll
            for (int l = 0; l < LBL; l++) part[warp][l] = p[l];
        }
    }
    __syncthreads();

    if (tid < 32) {
        float logit = -1e30f;
        if (tid < LBL) {
            float a = __ldg(cb + tid);
#pragma unroll
            for (int wz = 0; wz < 8; wz++) a += part[wz][tid];
            logit = a;
        }
        float m2 = logit;
#pragma unroll
        for (int ofs = 16; ofs; ofs >>= 1)
            m2 = fmaxf(m2, __shfl_xor_sync(0xffffffffu, m2, ofs));
        float ex = (tid < LBL) ? expf(logit - m2) : 0.f;
        float s2 = ex;
#pragma unroll
        for (int ofs = 16; ofs; ofs >>= 1)
            s2 += __shfl_xor_sync(0xffffffffu, s2, ofs);
        if (tid < LBL) out[tid] = logit - m2 - logf(s2);
    }
    __syncthreads();

    // reset for next graph replay
    __stcg(&g_num[tid], 0.f);
    if (tid < PL2) __stcg(&g_den[tid], 0.f);
    if (tid == 0) { __threadfence(); atomicExch(&g_cnt, 0u); }
}

// ---------------------------------------------------------------------------
extern "C" void kernel_launch(void* const* d_in, const int* in_sizes, int n_in,
                              void* d_out, int out_size) {
    const float* adj = (const float*)d_in[0];
    const float* wm  = (const float*)d_in[1];
    const float* w1  = (const float*)d_in[2];
    const float* b1  = (const float*)d_in[3];
    const float* w2  = (const float*)d_in[4];
    const float* b2  = (const float*)d_in[5];
    const float* p1  = (const float*)d_in[6];
    const float* pb1 = (const float*)d_in[7];
    const float* p2  = (const float*)d_in[8];
    const float* pb2 = (const float*)d_in[9];
    const float* cw  = (const float*)d_in[10];
    const float* cb  = (const float*)d_in[11];
    float* out = (float*)d_out;

    k_fused<<<GRID, 256>>>(adj, wm, w1, b1, w2, b2, p1, pb1, p2, pb2, cw, cb, out);
}

// round 13
// speedup vs baseline: 1.2753x; 1.0278x over previous
#include <cuda_runtime.h>

#define NN   2048
#define ORD  3
#define PTS  16
#define DIM1 64
#define DIM2 32
#define PL1  32
#define PL2  8
#define LBL  10
#define GRID 912                // 152 SMs x 6 resident blocks: exactly one wave

// Scratch (zero at module load; self-reset each launch)
__device__ float    g_num[PL2 * DIM2];
__device__ float    g_den[PL2];
__device__ unsigned g_row;      // row steal counter
__device__ unsigned g_done;     // block completion counter

__device__ __forceinline__ float fast_tanh(float x) {
    float r;
    asm("tanh.approx.f32 %0, %1;" : "=f"(r) : "f"(x));
    return r;
}

// cos(2*pi*y): exact reduction + even poly through (2*pi*t)^14, max err ~4e-6
__device__ __forceinline__ float cos2pi(float y) {
    float t = y - rintf(y);
    float u = t * t;
    float p = -1.7143907f;
    p = fmaf(p, u,  7.9035539f);
    p = fmaf(p, u, -26.4257337f);
    p = fmaf(p, u,  60.2446418f);
    p = fmaf(p, u, -85.4567987f);
    p = fmaf(p, u,  64.9393940f);
    p = fmaf(p, u, -19.7392088f);
    p = fmaf(p, u,  1.0f);
    return p;
}

__device__ __forceinline__ int bitrev3(int x) {
    return ((x & 1) << 2) | (x & 2) | ((x & 4) >> 2);
}

// ---------------------------------------------------------------------------
// Persistent fused kernel: 912 blocks steal rows until exhausted.
// Per row: R5 phase-1 (7 MUFU + 1 poly per 8-sweep) + R5 tail (MLP+pool).
// Last completed block computes the head and resets counters.
// ---------------------------------------------------------------------------
__global__ __launch_bounds__(256, 6) void k_fused(
    const float* __restrict__ adj, const float* __restrict__ wm,
    const float* __restrict__ w1, const float* __restrict__ b1,
    const float* __restrict__ w2, const float* __restrict__ b2,
    const float* __restrict__ p1, const float* __restrict__ pb1,
    const float* __restrict__ p2, const float* __restrict__ pb2,
    const float* __restrict__ cw, const float* __restrict__ cb,
    float* __restrict__ out) {

    const int tid = threadIdx.x;
    const int warp = tid >> 5, lane = tid & 31;

    __shared__ float s_w [ORD * PTS];
    __shared__ float s_ws[ORD * PTS];
    __shared__ float red[ORD][8][PTS];
    __shared__ float s_ms[ORD * PTS];
    __shared__ float s_h1[DIM1];
    __shared__ float s_h2[DIM2];
    __shared__ float s_ab[PL1];
    __shared__ float s_s[PL2];
    __shared__ int      s_r;
    __shared__ unsigned s_last;

    if (tid < ORD * PTS) {
        float w = wm[tid];
        s_w[tid]  = w;
        s_ws[tid] = w * 0.15915494309189535f;
    }
    // first steal folded into loop top

    for (;;) {
        if (tid == 0) s_r = (int)atomicAdd(&g_row, 1u);
        __syncthreads();                 // rendezvous: also orders smem reuse
        const int r = s_r;
        if (r >= NN) break;

        // ---- phase 1: characteristic features ----
        const float* base = adj + (size_t)r * NN;
#pragma unroll
        for (int o = 0; o < ORD; o++) {
            const float4* row = reinterpret_cast<const float4*>(base + (size_t)o * NN * NN);
            const float4 c0 = row[tid];
            const float4 c1 = row[tid + 256];
            const float xs[8] = {c0.x, c0.y, c0.z, c0.w, c1.x, c1.y, c1.z, c1.w};

#pragma unroll
            for (int s = 0; s < 2; s++) {
                float w[7], acc[8];
#pragma unroll
                for (int q = 0; q < 7; q++) { w[q] = s_w[o * PTS + s * 8 + q]; acc[q] = 0.f; }
                const float wsp = s_ws[o * PTS + s * 8 + 7];
                acc[7] = 0.f;

#pragma unroll
                for (int e = 0; e < 8; e++) {
                    const float x = xs[e];
#pragma unroll
                    for (int q = 0; q < 7; q++) acc[q] += __cosf(w[q] * x);
                    acc[7] += cos2pi(wsp * x);
                }

                // split-butterfly: 8 accs -> 1 per lane (point = bitrev3(lane&7))
#pragma unroll
                for (int st = 0; st < 3; st++) {
                    const int bit = 1 << st, half = 8 >> (st + 1);
                    const bool hi = lane & bit;
#pragma unroll
                    for (int q = 0; q < 4; q++) {
                        if (q < half) {
                            float send = hi ? acc[q] : acc[q + half];
                            float recv = __shfl_xor_sync(0xffffffffu, send, bit);
                            acc[q] = (hi ? acc[q + half] : acc[q]) + recv;
                        }
                    }
                }
                float v = acc[0];
                v += __shfl_xor_sync(0xffffffffu, v, 8);
                v += __shfl_xor_sync(0xffffffffu, v, 16);
                if (lane < 8) red[o][warp][s * 8 + lane] = v;
            }
        }
        __syncthreads();

        if (tid < ORD * PTS) {
            const int o = tid >> 4, l = tid & 15;
            float s = 0.f;
#pragma unroll
            for (int wz = 0; wz < 8; wz++) s += red[o][wz][l];
            s_ms[o * PTS + (l & 8) + bitrev3(l & 7)] = s * (1.0f / NN);
        }
        __syncthreads();

        // ---- tail: per-row MLP chain (weights L1-resident after row 1) ----
        if (tid < DIM1) {
            float a = __ldg(b1 + tid);
#pragma unroll
            for (int k = 0; k < ORD * PTS; k++) a = fmaf(s_ms[k], __ldg(w1 + k * DIM1 + tid), a);
            s_h1[tid] = fmaxf(a, 0.f);
        }
        __syncthreads();

        if (tid < DIM2) {
            float a = __ldg(b2 + tid);
#pragma unroll
            for (int k = 0; k < DIM1; k++) a = fmaf(s_h1[k], __ldg(w2 + k * DIM2 + tid), a);
            s_h2[tid] = fmaxf(a, 0.f);
        }
        __syncthreads();

        if (tid < PL1) {
            float a = __ldg(pb1 + tid);
#pragma unroll
            for (int k = 0; k < DIM2; k++) a = fmaf(s_h2[k], __ldg(p1 + k * PL1 + tid), a);
            s_ab[tid] = fast_tanh(a);
        }
        __syncthreads();

        if (tid < PL2) {
            float a = __ldg(pb2 + tid);
#pragma unroll
            for (int k = 0; k < PL1; k++) a = fmaf(s_ab[k], __ldg(p2 + k * PL2 + tid), a);
            s_s[tid] = a;
        }
        __syncthreads();

        // pooling contribution (|s| small: unshifted exp is safe)
        {
            const int c = tid >> 5, d = tid & 31;
            float e = __expf(s_s[c]);
            atomicAdd(&g_num[tid], e * s_h2[d]);
            if (d == 0) atomicAdd(&g_den[c], e);
        }
        // loop back: next steal's barrier orders smem reuse
    }

    // ---- block done; last block computes the head ----
    __threadfence();
    __syncthreads();
    if (tid == 0) s_last = (atomicAdd(&g_done, 1u) == GRID - 1u) ? 1u : 0u;
    __syncthreads();
    if (!s_last) return;

    __shared__ float part[8][LBL];
    {
        float v = __ldcg(&g_num[tid]) / __ldcg(&g_den[tid >> 5]);
        float p[LBL];
#pragma unroll
        for (int l = 0; l < LBL; l++) p[l] = v * __ldg(cw + tid * LBL + l);
#pragma unroll
        for (int ofs = 16; ofs; ofs >>= 1)
#pragma unroll
            for (int l = 0; l < LBL; l++)
                p[l] += __shfl_xor_sync(0xffffffffu, p[l], ofs);
        if (lane == 0) {
#pragma unroll
            for (int l = 0; l < LBL; l++) part[warp][l] = p[l];
        }
    }
    __syncthreads();

    if (tid < 32) {
        float logit = -1e30f;
        if (tid < LBL) {
            float a = __ldg(cb + tid);
#pragma unroll
            for (int wz = 0; wz < 8; wz++) a += part[wz][tid];
            logit = a;
        }
        float m2 = logit;
#pragma unroll
        for (int ofs = 16; ofs; ofs >>= 1)
            m2 = fmaxf(m2, __shfl_xor_sync(0xffffffffu, m2, ofs));
        float ex = (tid < LBL) ? expf(logit - m2) : 0.f;
        float s2 = ex;
#pragma unroll
        for (int ofs = 16; ofs; ofs >>= 1)
            s2 += __shfl_xor_sync(0xffffffffu, s2, ofs);
        if (tid < LBL) out[tid] = logit - m2 - logf(s2);
    }
    __syncthreads();

    // reset for next graph replay (all reads above complete)
    __stcg(&g_num[tid], 0.f);
    if (tid < PL2) __stcg(&g_den[tid], 0.f);
    if (tid == 0) {
        __threadfence();
        atomicExch(&g_row, 0u);
        atomicExch(&g_done, 0u);
    }
}

// ---------------------------------------------------------------------------
extern "C" void kernel_launch(void* const* d_in, const int* in_sizes, int n_in,
                              void* d_out, int out_size) {
    const float* adj = (const float*)d_in[0];
    const float* wm  = (const float*)d_in[1];
    const float* w1  = (const float*)d_in[2];
    const float* b1  = (const float*)d_in[3];
    const float* w2  = (const float*)d_in[4];
    const float* b2  = (const float*)d_in[5];
    const float* p1  = (const float*)d_in[6];
    const float* pb1 = (const float*)d_in[7];
    const float* p2  = (const float*)d_in[8];
    const float* pb2 = (const float*)d_in[9];
    const float* cw  = (const float*)d_in[10];
    const float* cb  = (const float*)d_in[11];
    float* out = (float*)d_out;

    k_fused<<<GRID, 256>>>(adj, wm, w1, b1, w2, b2, p1, pb1, p2, pb2, cw, cb, out);
}